// round 15
// baseline (speedup 1.0000x reference)
#include <cuda_runtime.h>
#include <cstdint>

// Problem constants
#define B_    512
#define U_    256
#define T_    256
#define NCW   2048   // 8*U

// 16 batch-groups x 8 unit-blocks = 128 persistent CTAs.
// CTA = 32 batch rows x 32 units (GEMM M=32, N=256, K=256), split into two
// pipelined half-steps of 16 rows each (halfA = rows 0-15, halfB = 16-31).
#define NBLK     128
#define NTHREADS 256
#define BM       32
#define GRP      8

// fp16 tiles, row pitch 264 fp16 = 528 B (132 words; 132 % 32 == 4)
#define LDWRD  132
#define A_OFF  0
#define B_OFF  16896               // 32*528
#define X_OFF  152064              // B_OFF + 256*528
#define XPITCH 260                 // floats; conflict-free x reads
#define SMEM_TOTAL 185344          // X_OFF + 32*260*4

// fp16 h slice staging: [parity][group][rank] -> 32 rows x 64B (2KB)
__device__ unsigned char g_hs[2 * 16 * GRP * 2048];
// per-(CTA,half,warp) flags: word cta*32 + half*16 + wid (one 128B line/CTA)
__device__ unsigned g_flag[16 * GRP * 32];
// monotonic ticket counters for the run-end barrier (never reset)
__device__ unsigned g_arrive[16 * 32];

// ---- helpers ---------------------------------------------------------------
__device__ __forceinline__ uint32_t smem_u32(const void* p) {
    uint32_t a;
    asm("{ .reg .u64 t; cvta.to.shared.u64 t, %1; cvt.u32.u64 %0, t; }"
        : "=r"(a) : "l"(p));
    return a;
}
__device__ __forceinline__ uint32_t hfpack(float hi, float lo) {
    uint32_t r;
    asm("cvt.rn.f16x2.f32 %0, %1, %2;" : "=r"(r) : "f"(hi), "f"(lo));
    return r;
}
__device__ __forceinline__ float sigf(float v) {
    return __fdividef(1.0f, 1.0f + __expf(-v));
}
__device__ __forceinline__ float tanhf_fast(float v) {
    return fmaf(2.0f, sigf(2.0f * v), -1.0f);
}
__device__ __forceinline__ void ldsm4(uint32_t* r, uint32_t addr) {
    asm volatile("ldmatrix.sync.aligned.m8n8.x4.shared.b16 {%0,%1,%2,%3}, [%4];"
                 : "=r"(r[0]), "=r"(r[1]), "=r"(r[2]), "=r"(r[3]) : "r"(addr));
}
__device__ __forceinline__ void mma16816(float* c, const uint32_t* a,
                                         uint32_t b0, uint32_t b1) {
    asm volatile(
        "mma.sync.aligned.m16n8k16.row.col.f32.f16.f16.f32 "
        "{%0,%1,%2,%3},{%4,%5,%6,%7},{%8,%9},{%0,%1,%2,%3};"
        : "+f"(c[0]), "+f"(c[1]), "+f"(c[2]), "+f"(c[3])
        : "r"(a[0]), "r"(a[1]), "r"(a[2]), "r"(a[3]), "r"(b0), "r"(b1));
}
__device__ __forceinline__ unsigned ld_acq(const unsigned* p) {
    unsigned v;
    asm volatile("ld.acquire.gpu.global.b32 %0, [%1];" : "=r"(v) : "l"(p) : "memory");
    return v;
}
__device__ __forceinline__ void st_rel(unsigned* p, unsigned v) {
    asm volatile("st.release.gpu.global.b32 [%0], %1;" :: "l"(p), "r"(v) : "memory");
}

extern __shared__ char smem[];

__global__ __launch_bounds__(NTHREADS, 1)
void nas_hmma(float* __restrict__ out,
              const float* __restrict__ W,
              const float* __restrict__ kern,
              const float* __restrict__ x)
{
    uint32_t* Bw = reinterpret_cast<uint32_t*>(smem + B_OFF);   // [256][LDWRD]
    float*    Xs = reinterpret_cast<float*>(smem + X_OFF);      // [32][XPITCH]

    const int tid  = threadIdx.x;
    const int wid  = tid >> 5;
    const int lane = tid & 31;
    const int quad = lane >> 2;
    const int ql   = lane & 3;
    const int bx   = blockIdx.x >> 3;   // batch group, 0..15
    const int by   = blockIdx.x & 7;    // unit block / rank, 0..7
    const int b0   = bx * BM;
    const int u0   = by * 32;

    const int uu = wid * 4 + ql;        // thread's CTA-local unit (0..31)

    // ---- Prologue: W -> permuted fp16 B tile; x -> smem; kern -> regs ------
    for (int i = 0; i < 128; i++) {
        int p  = tid + i * NTHREADS;
        int q  = p & 255;
        int kp = p >> 8;
        int g  = q >> 5;
        int u  = q & 31;
        int gcol = g * U_ + u0 + u;
        float w0 = W[(size_t)(2 * kp) * NCW + gcol];
        float w1 = W[(size_t)(2 * kp + 1) * NCW + gcol];
        int P = ((u >> 2) << 5) + ((g >> 1) << 3) + ((u & 3) << 1) + (g & 1);
        Bw[P * LDWRD + kp] = hfpack(w1, w0);
    }
    #pragma unroll
    for (int i = 0; i < 8; i++) {
        int idx = tid + i * NTHREADS;
        int row = idx >> 6;
        int q4  = idx & 63;
        float4 v = *reinterpret_cast<const float4*>(&x[(b0 + row) * U_ + q4 * 4]);
        *reinterpret_cast<float4*>(&Xs[row * XPITCH + q4 * 4]) = v;
    }
    float kr[8];
    #pragma unroll
    for (int g = 0; g < 8; g++)
        kr[g] = __ldg(&kern[g * U_ + u0 + uu]);
    __syncthreads();

    // ---- B -> registers, mma-fragment layout -------------------------------
    uint32_t breg[128];
    {
        const int Pb = wid * 32 + (lane >> 2);
        #pragma unroll
        for (int ks = 0; ks < 16; ks++)
            #pragma unroll
            for (int j = 0; j < 4; j++) {
                breg[ks * 8 + j * 2 + 0] = Bw[(Pb + j * 8) * LDWRD + ks * 8 + ql];
                breg[ks * 8 + j * 2 + 1] = Bw[(Pb + j * 8) * LDWRD + ks * 8 + 4 + ql];
            }
    }

    const uint32_t sbase = smem_u32(smem);
    // ldmatrix A bases: m-tile0 = rows 0-15, m-tile1 = rows 16-31
    const int rowA = ((lane >> 3) & 1) * 8 + (lane & 7);
    const uint32_t aBase0 = sbase + A_OFF + rowA * 528 + (lane >> 4) * 16;
    const uint32_t aBase1 = aBase0 + 16 * 528;

    // Copy assignment: warp rS (=wid) copies peer rS's half-slice (1KB/half);
    // lane -> row (lane>>1) within half, 32B chunk (lane&1).
    const int rS      = wid;
    const int rowHalf = lane >> 1;
    const int off32   = (lane & 1) * 32;
    const unsigned char* srcSlice = g_hs + ((size_t)(bx * GRP + rS)) * 2048;
    const uint32_t dstA = A_OFF + rowHalf * 528 + rS * 64 + off32;
    const uint32_t dstB = A_OFF + (16 + rowHalf) * 528 + rS * 64 + off32;
    const unsigned* flagPeerA = &g_flag[(bx * GRP + rS) * 32] + (lane & 7);
    const unsigned* flagPeerB = flagPeerA + 16;

    unsigned char* prodBase = g_hs + ((size_t)(bx * GRP + by)) * 2048;
    unsigned* flagOwnA = &g_flag[(bx * GRP + by) * 32 + wid];
    unsigned* flagOwnB = flagOwnA + 16;

    const size_t PAR = (size_t)16 * GRP * 2048;

    float creg[4] = {0.0f, 0.0f, 0.0f, 0.0f};
    __syncthreads();     // breg lifts done before any A-tile overwrite

    for (int t = 0; t < T_; t++) {
        const bool last = (t == T_ - 1);
        const size_t parIn  = (t & 1) ? PAR : 0;    // consume parity
        const size_t parOut = (t & 1) ? 0 : PAR;    // produce parity
        unsigned char* prod = prodBase + parOut;

        float acc0[4][4], acc1[4][4];
        #pragma unroll
        for (int j = 0; j < 4; j++)
            #pragma unroll
            for (int v = 0; v < 4; v++) { acc0[j][v] = 0.0f; acc1[j][v] = 0.0f; }

        // ============ half A: poll, copy, GEMM m0 ===========================
        if (t > 0) {
            for (;;) {
                unsigned v = (lane < 8) ? ld_acq(flagPeerA) : (unsigned)t;
                if (__all_sync(0xffffffffu, (int)(v - (unsigned)t) >= 0)) break;
            }
            const unsigned char* src = srcSlice + parIn + rowHalf * 64 + off32;
            float4 v0 = __ldcg(reinterpret_cast<const float4*>(src));
            float4 v1 = __ldcg(reinterpret_cast<const float4*>(src) + 1);
            *reinterpret_cast<float4*>(smem + dstA)      = v0;
            *reinterpret_cast<float4*>(smem + dstA + 16) = v1;
            __syncthreads();
            #pragma unroll
            for (int ks = 0; ks < 16; ks++) {
                uint32_t a[4];
                ldsm4(a, aBase0 + ks * 32);
                #pragma unroll
                for (int j = 0; j < 4; j++)
                    mma16816(acc0[j], a, breg[ks * 8 + j * 2],
                             breg[ks * 8 + j * 2 + 1]);
            }
        }

        // ---- epilogue rows 0-15 (creg[0..1]) + early publish A -------------
        #pragma unroll
        for (int rr = 0; rr < 2; rr++) {
            const int row = rr * 8 + quad;
            float xv = Xs[row * XPITCH + t];
            float i0 = xv * kr[0], m0 = acc0[0][rr * 2 + 0];
            float i1 = xv * kr[1], m1 = acc0[0][rr * 2 + 1];
            float i2 = xv * kr[2], m2 = acc0[1][rr * 2 + 0];
            float i3 = xv * kr[3], m3 = acc0[1][rr * 2 + 1];
            float i4 = xv * kr[4], m4 = acc0[2][rr * 2 + 0];
            float i5 = xv * kr[5], m5 = acc0[2][rr * 2 + 1];
            float i6 = xv * kr[6], m6 = acc0[3][rr * 2 + 0];
            float i7 = xv * kr[7], m7 = acc0[3][rr * 2 + 1];

            float l10 = sigf(i0 + m0);
            float l11 = fmaxf(i1 + m1, 0.0f);
            float l12 = sigf(i2 + m2);
            float l13 = fmaxf(i3 * m3, 0.0f);
            float l14 = tanhf_fast(i4 + m4);
            float l15 = sigf(i5 + m5);
            float l16 = tanhf_fast(i6 + m6);
            float l17 = sigf(i7 + m7);
            float l20 = tanhf_fast(l10 * l11);
            float l21 = tanhf_fast(l12 + l13);
            float l22 = tanhf_fast(l14 * l15);
            float l23 = sigf(l16 + l17);
            l20 = tanhf_fast(l20 + creg[rr]);
            float nc  = l20 * l21;
            float l31 = tanhf_fast(l22 + l23);
            float nh  = tanhf_fast(nc * l31);
            creg[rr] = nc;

            if (last) {
                out[(b0 + row) * U_ + u0 + uu] = nh;
            } else {
                float other = __shfl_xor_sync(0xffffffffu, nh, 1);
                if ((ql & 1) == 0)
                    *reinterpret_cast<uint32_t*>(prod + row * 64 + uu * 2) =
                        hfpack(other, nh);
            }
        }
        if (!last) {
            __syncwarp();
            if (lane == 0) st_rel(flagOwnA, (unsigned)(t + 1));
        }

        // ============ half B: poll, copy, GEMM m1 ===========================
        if (t > 0) {
            for (;;) {
                unsigned v = (lane < 8) ? ld_acq(flagPeerB) : (unsigned)t;
                if (__all_sync(0xffffffffu, (int)(v - (unsigned)t) >= 0)) break;
            }
            const unsigned char* src = srcSlice + parIn + (16 + rowHalf) * 64 + off32;
            float4 v0 = __ldcg(reinterpret_cast<const float4*>(src));
            float4 v1 = __ldcg(reinterpret_cast<const float4*>(src) + 1);
            *reinterpret_cast<float4*>(smem + dstB)      = v0;
            *reinterpret_cast<float4*>(smem + dstB + 16) = v1;
            __syncthreads();
            #pragma unroll
            for (int ks = 0; ks < 16; ks++) {
                uint32_t a[4];
                ldsm4(a, aBase1 + ks * 32);
                #pragma unroll
                for (int j = 0; j < 4; j++)
                    mma16816(acc1[j], a, breg[ks * 8 + j * 2],
                             breg[ks * 8 + j * 2 + 1]);
            }
        }

        // ---- epilogue rows 16-31 (creg[2..3]) + publish B ------------------
        #pragma unroll
        for (int rr = 0; rr < 2; rr++) {
            const int row = 16 + rr * 8 + quad;
            float xv = Xs[row * XPITCH + t];
            float i0 = xv * kr[0], m0 = acc1[0][rr * 2 + 0];
            float i1 = xv * kr[1], m1 = acc1[0][rr * 2 + 1];
            float i2 = xv * kr[2], m2 = acc1[1][rr * 2 + 0];
            float i3 = xv * kr[3], m3 = acc1[1][rr * 2 + 1];
            float i4 = xv * kr[4], m4 = acc1[2][rr * 2 + 0];
            float i5 = xv * kr[5], m5 = acc1[2][rr * 2 + 1];
            float i6 = xv * kr[6], m6 = acc1[3][rr * 2 + 0];
            float i7 = xv * kr[7], m7 = acc1[3][rr * 2 + 1];

            float l10 = sigf(i0 + m0);
            float l11 = fmaxf(i1 + m1, 0.0f);
            float l12 = sigf(i2 + m2);
            float l13 = fmaxf(i3 * m3, 0.0f);
            float l14 = tanhf_fast(i4 + m4);
            float l15 = sigf(i5 + m5);
            float l16 = tanhf_fast(i6 + m6);
            float l17 = sigf(i7 + m7);
            float l20 = tanhf_fast(l10 * l11);
            float l21 = tanhf_fast(l12 + l13);
            float l22 = tanhf_fast(l14 * l15);
            float l23 = sigf(l16 + l17);
            l20 = tanhf_fast(l20 + creg[2 + rr]);
            float nc  = l20 * l21;
            float l31 = tanhf_fast(l22 + l23);
            float nh  = tanhf_fast(nc * l31);
            creg[2 + rr] = nc;

            if (last) {
                out[(b0 + row) * U_ + u0 + uu] = nh;
            } else {
                float other = __shfl_xor_sync(0xffffffffu, nh, 1);
                if ((ql & 1) == 0)
                    *reinterpret_cast<uint32_t*>(prod + row * 64 + uu * 2) =
                        hfpack(other, nh);
            }
        }
        if (!last) {
            __syncwarp();
            if (lane == 0) st_rel(flagOwnB, (unsigned)(t + 1));
        }
    }

    // ---- Run-end: monotonic ticket barrier, then reset flags for replay ----
    __syncthreads();
    if (tid == 0) {
        unsigned* ctr = &g_arrive[bx * 32];
        __threadfence();
        unsigned ticket = atomicAdd(ctr, 1u);
        unsigned target = (ticket & ~(GRP - 1u)) + GRP;
        volatile unsigned* p = ctr;
        while ((int)(*p - target) < 0) { }
        #pragma unroll
        for (int w = 0; w < 32; w++)
            g_flag[(bx * GRP + by) * 32 + w] = 0u;
        __threadfence();
    }
}

extern "C" void kernel_launch(void* const* d_in, const int* in_sizes, int n_in,
                              void* d_out, int out_size) {
    const float* x    = nullptr;
    const float* kern = nullptr;
    const float* W    = nullptr;
    for (int i = 0; i < n_in; i++) {
        if (in_sizes[i] == B_ * U_)       x    = (const float*)d_in[i];
        else if (in_sizes[i] == 8 * U_)   kern = (const float*)d_in[i];
        else if (in_sizes[i] == U_ * NCW) W    = (const float*)d_in[i];
    }
    float* out = (float*)d_out;

    cudaFuncSetAttribute(nas_hmma, cudaFuncAttributeMaxDynamicSharedMemorySize,
                         SMEM_TOTAL);
    nas_hmma<<<NBLK, NTHREADS, SMEM_TOTAL>>>(out, W, kern, x);
}

// round 16
// speedup vs baseline: 1.2858x; 1.2858x over previous
#include <cuda_runtime.h>
#include <cstdint>

// Problem constants
#define B_    512
#define U_    256
#define T_    256
#define NCW   2048   // 8*U

// 16 batch-groups x 8 unit-blocks = 128 persistent CTAs.
// CTA = 32 batch rows x 32 units (GEMM M=32, N=256, K=256).
#define NBLK     128
#define NTHREADS 256
#define BM       32
#define GRP      8

// fp16 tiles, row pitch 264 fp16 = 528 B (132 words; 132 % 32 == 4)
#define LDWRD  132
#define A_OFF  0
#define B_OFF  16896               // 32*528
#define X_OFF  152064              // B_OFF + 256*528
#define XPITCH 260                 // floats; conflict-free x reads
#define SMEM_TOTAL 185344          // X_OFF + 32*260*4

// fp16 h slice staging: [parity][group][rank] -> 32 rows x 32 units f16 (2KB)
__device__ unsigned char g_hs[2 * 16 * GRP * 2048];
// per-CTA step flags (own 128B line each); reset to 0 at run end (replay-safe)
__device__ unsigned g_flag[16 * GRP * 32];
// monotonic ticket counters for the run-end barrier (never reset)
__device__ unsigned g_arrive[16 * 32];

// ---- helpers ---------------------------------------------------------------
__device__ __forceinline__ uint32_t smem_u32(const void* p) {
    uint32_t a;
    asm("{ .reg .u64 t; cvta.to.shared.u64 t, %1; cvt.u32.u64 %0, t; }"
        : "=r"(a) : "l"(p));
    return a;
}
__device__ __forceinline__ uint32_t hfpack(float hi, float lo) {
    uint32_t r;
    asm("cvt.rn.f16x2.f32 %0, %1, %2;" : "=r"(r) : "f"(hi), "f"(lo));
    return r;
}
// ---- activations -----------------------------------------------------------
// MUFU.TANH (1 MUFU) for internal gates; accurate 2-MUFU tanh for the output.
__device__ __forceinline__ float tanh_ap(float v) {
    float r;
    asm("tanh.approx.f32 %0, %1;" : "=f"(r) : "f"(v));
    return r;
}
__device__ __forceinline__ float sig_ap(float v) {
    return fmaf(0.5f, tanh_ap(0.5f * v), 0.5f);
}
__device__ __forceinline__ float tanh_acc(float v) {
    float s = __fdividef(1.0f, 1.0f + __expf(-2.0f * v));
    return fmaf(2.0f, s, -1.0f);
}
__device__ __forceinline__ void ldsm4(uint32_t* r, uint32_t addr) {
    asm volatile("ldmatrix.sync.aligned.m8n8.x4.shared.b16 {%0,%1,%2,%3}, [%4];"
                 : "=r"(r[0]), "=r"(r[1]), "=r"(r[2]), "=r"(r[3]) : "r"(addr));
}
__device__ __forceinline__ void mma16816(float* c, const uint32_t* a,
                                         uint32_t b0, uint32_t b1) {
    asm volatile(
        "mma.sync.aligned.m16n8k16.row.col.f32.f16.f16.f32 "
        "{%0,%1,%2,%3},{%4,%5,%6,%7},{%8,%9},{%0,%1,%2,%3};"
        : "+f"(c[0]), "+f"(c[1]), "+f"(c[2]), "+f"(c[3])
        : "r"(a[0]), "r"(a[1]), "r"(a[2]), "r"(a[3]), "r"(b0), "r"(b1));
}
__device__ __forceinline__ unsigned ld_acq(const unsigned* p) {
    unsigned v;
    asm volatile("ld.acquire.gpu.global.b32 %0, [%1];" : "=r"(v) : "l"(p) : "memory");
    return v;
}

extern __shared__ char smem[];

__global__ __launch_bounds__(NTHREADS, 1)
void nas_hmma(float* __restrict__ out,
              const float* __restrict__ W,
              const float* __restrict__ kern,
              const float* __restrict__ x)
{
    uint32_t* Bw = reinterpret_cast<uint32_t*>(smem + B_OFF);   // [256][LDWRD]
    float*    Xs = reinterpret_cast<float*>(smem + X_OFF);      // [32][XPITCH]

    const int tid  = threadIdx.x;
    const int wid  = tid >> 5;
    const int lane = tid & 31;
    const int quad = lane >> 2;
    const int ql   = lane & 3;
    const int bx   = blockIdx.x >> 3;   // batch group, 0..15
    const int by   = blockIdx.x & 7;    // unit block / rank, 0..7
    const int b0   = bx * BM;
    const int u0   = by * 32;

    const int uu = wid * 4 + ql;        // thread's CTA-local unit (0..31)

    // ---- Prologue ----------------------------------------------------------
    // W slice -> fp16 B tile with gate-interleaved column permutation:
    // logical col q = g*32+u -> physical P = (u>>2)*32 + (g>>1)*8 + (u&3)*2 + (g&1)
    for (int i = 0; i < 128; i++) {
        int p  = tid + i * NTHREADS;
        int q  = p & 255;
        int kp = p >> 8;
        int g  = q >> 5;
        int u  = q & 31;
        int gcol = g * U_ + u0 + u;
        float w0 = W[(size_t)(2 * kp) * NCW + gcol];
        float w1 = W[(size_t)(2 * kp + 1) * NCW + gcol];
        int P = ((u >> 2) << 5) + ((g >> 1) << 3) + ((u & 3) << 1) + (g & 1);
        Bw[P * LDWRD + kp] = hfpack(w1, w0);
    }
    // x slice [32 rows x 256 t] -> smem
    #pragma unroll
    for (int i = 0; i < 8; i++) {
        int idx = tid + i * NTHREADS;
        int row = idx >> 6;
        int q4  = idx & 63;
        float4 v = *reinterpret_cast<const float4*>(&x[(b0 + row) * U_ + q4 * 4]);
        *reinterpret_cast<float4*>(&Xs[row * XPITCH + q4 * 4]) = v;
    }
    float kr[8];
    #pragma unroll
    for (int g = 0; g < 8; g++)
        kr[g] = __ldg(&kern[g * U_ + u0 + uu]);
    __syncthreads();

    // ---- B -> registers, mma-fragment layout --------------------------------
    uint32_t breg[128];
    {
        const int Pb = wid * 32 + (lane >> 2);
        #pragma unroll
        for (int ks = 0; ks < 16; ks++)
            #pragma unroll
            for (int j = 0; j < 4; j++) {
                breg[ks * 8 + j * 2 + 0] = Bw[(Pb + j * 8) * LDWRD + ks * 8 + ql];
                breg[ks * 8 + j * 2 + 1] = Bw[(Pb + j * 8) * LDWRD + ks * 8 + 4 + ql];
            }
    }

    const uint32_t sbase = smem_u32(smem);
    // ldmatrix base addresses for A (advance 32B per 16-k step)
    const int rowA = ((lane >> 3) & 1) * 8 + (lane & 7);
    const uint32_t aBase0 = sbase + A_OFF + rowA * 528 + (lane >> 4) * 16;
    const uint32_t aBase1 = aBase0 + 16 * 528;

    // Copy assignment: warp rS (=wid) copies peer rS's slice; thread: 64B.
    const int rS   = wid;
    const int rowS = lane;
    const unsigned char* srcS =
        g_hs + ((size_t)(bx * GRP + rS)) * 2048 + rowS * 64;   // + parity sel
    const uint32_t dstOff = A_OFF + rowS * 528 + rS * 64;
    const unsigned* flagS = &g_flag[(bx * GRP + rS) * 32];

    // Producer slice base for this CTA
    unsigned char* prodBase = g_hs + ((size_t)(bx * GRP + by)) * 2048;
    unsigned* flagOwn = &g_flag[(bx * GRP + by) * 32];

    float creg[4] = {0.0f, 0.0f, 0.0f, 0.0f};
    __syncthreads();     // breg lifts done before any A-tile overwrite

    for (int t = 0; t < T_; t++) {
        float acc[2][4][4];
        #pragma unroll
        for (int mt = 0; mt < 2; mt++)
            #pragma unroll
            for (int j = 0; j < 4; j++)
                #pragma unroll
                for (int v = 0; v < 4; v++)
                    acc[mt][j][v] = 0.0f;

        if (t > 0) {
            // ---- wait for peer slice, copy 64B into A tile -----------------
            while ((int)(ld_acq(flagS) - (unsigned)t) < 0) { }
            const unsigned char* src = srcS + ((t & 1) ? 1 : 0) * (16 * GRP * 2048);
            float4 v0 = __ldcg(reinterpret_cast<const float4*>(src));
            float4 v1 = __ldcg(reinterpret_cast<const float4*>(src) + 1);
            float4 v2 = __ldcg(reinterpret_cast<const float4*>(src) + 2);
            float4 v3 = __ldcg(reinterpret_cast<const float4*>(src) + 3);
            *reinterpret_cast<float4*>(smem + dstOff)      = v0;
            *reinterpret_cast<float4*>(smem + dstOff + 16) = v1;
            *reinterpret_cast<float4*>(smem + dstOff + 32) = v2;
            *reinterpret_cast<float4*>(smem + dstOff + 48) = v3;
            __syncthreads();

            // ---- HMMA GEMM: M=32, N=256, K=256; B in registers -------------
            #pragma unroll
            for (int ks = 0; ks < 16; ks++) {
                uint32_t a0[4], a1[4];
                ldsm4(a0, aBase0 + ks * 32);
                ldsm4(a1, aBase1 + ks * 32);
                #pragma unroll
                for (int j = 0; j < 4; j++) {
                    mma16816(acc[0][j], a0, breg[ks * 8 + j * 2],
                             breg[ks * 8 + j * 2 + 1]);
                    mma16816(acc[1][j], a1, breg[ks * 8 + j * 2],
                             breg[ks * 8 + j * 2 + 1]);
                }
            }
        }

        // ---- NASCell epilogue: 4 rows x 1 unit per thread ------------------
        // Internal gates: 1-MUFU tanh.approx; output nh: accurate 2-MUFU tanh.
        unsigned char* prod = prodBase + ((t & 1) ? 0 : 1) * (16 * GRP * 2048);
        #pragma unroll
        for (int rr = 0; rr < 4; rr++) {
            const int mt   = rr >> 1;
            const int rsel = rr & 1;
            const int row  = mt * 16 + rsel * 8 + quad;
            float xv = Xs[row * XPITCH + t];

            float i0 = xv * kr[0], m0 = acc[mt][0][rsel * 2 + 0];
            float i1 = xv * kr[1], m1 = acc[mt][0][rsel * 2 + 1];
            float i2 = xv * kr[2], m2 = acc[mt][1][rsel * 2 + 0];
            float i3 = xv * kr[3], m3 = acc[mt][1][rsel * 2 + 1];
            float i4 = xv * kr[4], m4 = acc[mt][2][rsel * 2 + 0];
            float i5 = xv * kr[5], m5 = acc[mt][2][rsel * 2 + 1];
            float i6 = xv * kr[6], m6 = acc[mt][3][rsel * 2 + 0];
            float i7 = xv * kr[7], m7 = acc[mt][3][rsel * 2 + 1];

            float l10 = sig_ap(i0 + m0);
            float l11 = fmaxf(i1 + m1, 0.0f);
            float l12 = sig_ap(i2 + m2);
            float l13 = fmaxf(i3 * m3, 0.0f);
            float l14 = tanh_ap(i4 + m4);
            float l15 = sig_ap(i5 + m5);
            float l16 = tanh_ap(i6 + m6);
            float l17 = sig_ap(i7 + m7);

            float l20 = tanh_ap(l10 * l11);
            float l21 = tanh_ap(l12 + l13);
            float l22 = tanh_ap(l14 * l15);
            float l23 = sig_ap(l16 + l17);

            l20 = tanh_ap(l20 + creg[rr]);
            float nc  = l20 * l21;
            float l31 = tanh_ap(l22 + l23);
            float nh  = tanh_acc(nc * l31);
            creg[rr] = nc;

            if (t == T_ - 1) {
                out[(b0 + row) * U_ + u0 + uu] = nh;
            } else {
                float other = __shfl_xor_sync(0xffffffffu, nh, 1);
                if ((ql & 1) == 0) {
                    uint32_t pk = hfpack(other, nh);   // {uu+1, uu}
                    *reinterpret_cast<uint32_t*>(prod + row * 64 + uu * 2) = pk;
                }
            }
        }

        if (t != T_ - 1) {
            __threadfence();        // publish slice stores
            __syncthreads();        // all threads' stores fenced; GEMM t done
            if (tid == 0) {
                asm volatile("st.relaxed.gpu.global.b32 [%0], %1;"
                             :: "l"(flagOwn), "r"((unsigned)(t + 1)) : "memory");
            }
        }
    }

    // ---- Run-end: monotonic ticket barrier, then reset flags for replay ----
    __syncthreads();
    if (tid == 0) {
        unsigned* ctr = &g_arrive[bx * 32];
        __threadfence();
        unsigned ticket = atomicAdd(ctr, 1u);
        unsigned target = (ticket & ~(GRP - 1u)) + GRP;
        volatile unsigned* p = ctr;
        while ((int)(*p - target) < 0) { }
        *flagOwn = 0u;              // safe: all group CTAs past final polls
        __threadfence();
    }
}

extern "C" void kernel_launch(void* const* d_in, const int* in_sizes, int n_in,
                              void* d_out, int out_size) {
    const float* x    = nullptr;
    const float* kern = nullptr;
    const float* W    = nullptr;
    for (int i = 0; i < n_in; i++) {
        if (in_sizes[i] == B_ * U_)       x    = (const float*)d_in[i];
        else if (in_sizes[i] == 8 * U_)   kern = (const float*)d_in[i];
        else if (in_sizes[i] == U_ * NCW) W    = (const float*)d_in[i];
    }
    float* out = (float*)d_out;

    cudaFuncSetAttribute(nas_hmma, cudaFuncAttributeMaxDynamicSharedMemorySize,
                         SMEM_TOTAL);
    nas_hmma<<<NBLK, NTHREADS, SMEM_TOTAL>>>(out, W, kern, x);
}

// round 17
// speedup vs baseline: 1.3962x; 1.0859x over previous
#include <cuda_runtime.h>
#include <cuda_fp16.h>
#include <cstdint>

// Problem constants
#define B_    512
#define U_    256
#define T_    256
#define NCW   2048   // 8*U

// 16 batch-groups x 8 unit-blocks = 128 persistent CTAs.
// CTA = 32 batch rows x 32 units (GEMM M=32, N=256, K=256).
#define NBLK     128
#define NTHREADS 256
#define BM       32
#define GRP      8

// fp16 tiles, row pitch 264 fp16 = 528 B (132 words; 132 % 32 == 4)
#define LDWRD  132
#define A_OFF  0
#define B_OFF  16896               // 32*528
#define X_OFF  152064              // B_OFF + 256*528
#define XPITCH 260                 // floats; conflict-free x reads
#define SMEM_TOTAL 185344          // X_OFF + 32*260*4

// fp16 h slice staging: [parity][group][rank] -> 32 rows x 32 units f16 (2KB)
__device__ unsigned char g_hs[2 * 16 * GRP * 2048];
// per-CTA step flags (own 128B line each); reset to 0 at run end (replay-safe)
__device__ unsigned g_flag[16 * GRP * 32];
// monotonic ticket counters for the run-end barrier (never reset)
__device__ unsigned g_arrive[16 * 32];

// ---- helpers ---------------------------------------------------------------
__device__ __forceinline__ uint32_t smem_u32(const void* p) {
    uint32_t a;
    asm("{ .reg .u64 t; cvta.to.shared.u64 t, %1; cvt.u32.u64 %0, t; }"
        : "=r"(a) : "l"(p));
    return a;
}
__device__ __forceinline__ uint32_t hfpack(float hi, float lo) {
    uint32_t r;
    asm("cvt.rn.f16x2.f32 %0, %1, %2;" : "=r"(r) : "f"(hi), "f"(lo));
    return r;
}
// pack {lo, hi} floats -> half2 (lo at lower half)
__device__ __forceinline__ __half2 pack2h(float lo, float hi) {
    uint32_t u;
    asm("cvt.rn.f16x2.f32 %0, %1, %2;" : "=r"(u) : "f"(hi), "f"(lo));
    return *reinterpret_cast<__half2*>(&u);
}
// ---- activations -----------------------------------------------------------
__device__ __forceinline__ float tanh_ap(float v) {
    float r;
    asm("tanh.approx.f32 %0, %1;" : "=f"(r) : "f"(v));
    return r;
}
__device__ __forceinline__ float sig_ap(float v) {
    return fmaf(0.5f, tanh_ap(0.5f * v), 0.5f);
}
__device__ __forceinline__ float tanh_acc(float v) {
    float s = __fdividef(1.0f, 1.0f + __expf(-2.0f * v));
    return fmaf(2.0f, s, -1.0f);
}
__device__ __forceinline__ __half2 tanh2_ap(__half2 v) {
    uint32_t r;
    asm("tanh.approx.f16x2 %0, %1;"
        : "=r"(r) : "r"(*reinterpret_cast<const uint32_t*>(&v)));
    return *reinterpret_cast<__half2*>(&r);
}
__device__ __forceinline__ __half2 sig2_ap(__half2 v) {
    const __half2 h = __float2half2_rn(0.5f);
    return __hfma2(h, tanh2_ap(__hmul2(v, h)), h);
}
__device__ __forceinline__ void ldsm4(uint32_t* r, uint32_t addr) {
    asm volatile("ldmatrix.sync.aligned.m8n8.x4.shared.b16 {%0,%1,%2,%3}, [%4];"
                 : "=r"(r[0]), "=r"(r[1]), "=r"(r[2]), "=r"(r[3]) : "r"(addr));
}
__device__ __forceinline__ void mma16816(float* c, const uint32_t* a,
                                         uint32_t b0, uint32_t b1) {
    asm volatile(
        "mma.sync.aligned.m16n8k16.row.col.f32.f16.f16.f32 "
        "{%0,%1,%2,%3},{%4,%5,%6,%7},{%8,%9},{%0,%1,%2,%3};"
        : "+f"(c[0]), "+f"(c[1]), "+f"(c[2]), "+f"(c[3])
        : "r"(a[0]), "r"(a[1]), "r"(a[2]), "r"(a[3]), "r"(b0), "r"(b1));
}
__device__ __forceinline__ unsigned ld_acq(const unsigned* p) {
    unsigned v;
    asm volatile("ld.acquire.gpu.global.b32 %0, [%1];" : "=r"(v) : "l"(p) : "memory");
    return v;
}

extern __shared__ char smem[];

__global__ __launch_bounds__(NTHREADS, 1)
void nas_hmma(float* __restrict__ out,
              const float* __restrict__ W,
              const float* __restrict__ kern,
              const float* __restrict__ x)
{
    uint32_t* Bw = reinterpret_cast<uint32_t*>(smem + B_OFF);   // [256][LDWRD]
    float*    Xs = reinterpret_cast<float*>(smem + X_OFF);      // [32][XPITCH]

    const int tid  = threadIdx.x;
    const int wid  = tid >> 5;
    const int lane = tid & 31;
    const int quad = lane >> 2;
    const int ql   = lane & 3;
    const int bx   = blockIdx.x >> 3;   // batch group, 0..15
    const int by   = blockIdx.x & 7;    // unit block / rank, 0..7
    const int b0   = bx * BM;
    const int u0   = by * 32;

    const int uu = wid * 4 + ql;        // thread's CTA-local unit (0..31)

    // ---- Prologue ----------------------------------------------------------
    // W slice -> fp16 B tile with gate-interleaved column permutation:
    // logical col q = g*32+u -> physical P = (u>>2)*32 + (g>>1)*8 + (u&3)*2 + (g&1)
    for (int i = 0; i < 128; i++) {
        int p  = tid + i * NTHREADS;
        int q  = p & 255;
        int kp = p >> 8;
        int g  = q >> 5;
        int u  = q & 31;
        int gcol = g * U_ + u0 + u;
        float w0 = W[(size_t)(2 * kp) * NCW + gcol];
        float w1 = W[(size_t)(2 * kp + 1) * NCW + gcol];
        int P = ((u >> 2) << 5) + ((g >> 1) << 3) + ((u & 3) << 1) + (g & 1);
        Bw[P * LDWRD + kp] = hfpack(w1, w0);
    }
    // x slice [32 rows x 256 t] -> smem
    #pragma unroll
    for (int i = 0; i < 8; i++) {
        int idx = tid + i * NTHREADS;
        int row = idx >> 6;
        int q4  = idx & 63;
        float4 v = *reinterpret_cast<const float4*>(&x[(b0 + row) * U_ + q4 * 4]);
        *reinterpret_cast<float4*>(&Xs[row * XPITCH + q4 * 4]) = v;
    }
    float kr[8];
    __half2 kr2[8];
    #pragma unroll
    for (int g = 0; g < 8; g++) {
        kr[g]  = __ldg(&kern[g * U_ + u0 + uu]);
        kr2[g] = __float2half2_rn(kr[g]);
    }
    __syncthreads();

    // ---- B -> registers, mma-fragment layout --------------------------------
    uint32_t breg[128];
    {
        const int Pb = wid * 32 + (lane >> 2);
        #pragma unroll
        for (int ks = 0; ks < 16; ks++)
            #pragma unroll
            for (int j = 0; j < 4; j++) {
                breg[ks * 8 + j * 2 + 0] = Bw[(Pb + j * 8) * LDWRD + ks * 8 + ql];
                breg[ks * 8 + j * 2 + 1] = Bw[(Pb + j * 8) * LDWRD + ks * 8 + 4 + ql];
            }
    }

    const uint32_t sbase = smem_u32(smem);
    // ldmatrix base addresses for A (advance 32B per 16-k step)
    const int rowA_ = ((lane >> 3) & 1) * 8 + (lane & 7);
    const uint32_t aBase0 = sbase + A_OFF + rowA_ * 528 + (lane >> 4) * 16;
    const uint32_t aBase1 = aBase0 + 16 * 528;

    // Copy assignment: warp rS (=wid) copies peer rS's slice; thread: 64B.
    const int rS   = wid;
    const int rowS = lane;
    const unsigned char* srcS =
        g_hs + ((size_t)(bx * GRP + rS)) * 2048 + rowS * 64;   // + parity sel
    const uint32_t dstOff = A_OFF + rowS * 528 + rS * 64;
    const unsigned* flagS = &g_flag[(bx * GRP + rS) * 32];

    // Producer slice base for this CTA
    unsigned char* prodBase = g_hs + ((size_t)(bx * GRP + by)) * 2048;
    unsigned* flagOwn = &g_flag[(bx * GRP + by) * 32];

    __half2 c2[2];                      // c, row-paired fp16 (lo=rowA, hi=rowB)
    c2[0] = __float2half2_rn(0.0f);
    c2[1] = __float2half2_rn(0.0f);
    __syncthreads();     // breg lifts done before any A-tile overwrite

    for (int t = 0; t < T_; t++) {
        float acc[2][4][4];
        #pragma unroll
        for (int mt = 0; mt < 2; mt++)
            #pragma unroll
            for (int j = 0; j < 4; j++)
                #pragma unroll
                for (int v = 0; v < 4; v++)
                    acc[mt][j][v] = 0.0f;

        if (t > 0) {
            // ---- wait for peer slice, copy 64B into A tile -----------------
            while ((int)(ld_acq(flagS) - (unsigned)t) < 0) { }
            const unsigned char* src = srcS + ((t & 1) ? 1 : 0) * (16 * GRP * 2048);
            float4 v0 = __ldcg(reinterpret_cast<const float4*>(src));
            float4 v1 = __ldcg(reinterpret_cast<const float4*>(src) + 1);
            float4 v2 = __ldcg(reinterpret_cast<const float4*>(src) + 2);
            float4 v3 = __ldcg(reinterpret_cast<const float4*>(src) + 3);
            *reinterpret_cast<float4*>(smem + dstOff)      = v0;
            *reinterpret_cast<float4*>(smem + dstOff + 16) = v1;
            *reinterpret_cast<float4*>(smem + dstOff + 32) = v2;
            *reinterpret_cast<float4*>(smem + dstOff + 48) = v3;
            __syncthreads();

            // ---- HMMA GEMM: M=32, N=256, K=256; B in registers -------------
            #pragma unroll
            for (int ks = 0; ks < 16; ks++) {
                uint32_t a0[4], a1[4];
                ldsm4(a0, aBase0 + ks * 32);
                ldsm4(a1, aBase1 + ks * 32);
                #pragma unroll
                for (int j = 0; j < 4; j++) {
                    mma16816(acc[0][j], a0, breg[ks * 8 + j * 2],
                             breg[ks * 8 + j * 2 + 1]);
                    mma16816(acc[1][j], a1, breg[ks * 8 + j * 2],
                             breg[ks * 8 + j * 2 + 1]);
                }
            }
        }

        if (t == T_ - 1) {
            // ---- Final step: full fp32 epilogue (output precision) ---------
            #pragma unroll
            for (int rr = 0; rr < 4; rr++) {
                const int mt   = rr >> 1;
                const int rsel = rr & 1;
                const int row  = mt * 16 + rsel * 8 + quad;
                float xv  = Xs[row * XPITCH + t];
                float cin = (rsel == 0) ? __low2float(c2[mt])
                                        : __high2float(c2[mt]);

                float i0 = xv * kr[0], m0 = acc[mt][0][rsel * 2 + 0];
                float i1 = xv * kr[1], m1 = acc[mt][0][rsel * 2 + 1];
                float i2 = xv * kr[2], m2 = acc[mt][1][rsel * 2 + 0];
                float i3 = xv * kr[3], m3 = acc[mt][1][rsel * 2 + 1];
                float i4 = xv * kr[4], m4 = acc[mt][2][rsel * 2 + 0];
                float i5 = xv * kr[5], m5 = acc[mt][2][rsel * 2 + 1];
                float i6 = xv * kr[6], m6 = acc[mt][3][rsel * 2 + 0];
                float i7 = xv * kr[7], m7 = acc[mt][3][rsel * 2 + 1];

                float l10 = sig_ap(i0 + m0);
                float l11 = fmaxf(i1 + m1, 0.0f);
                float l12 = sig_ap(i2 + m2);
                float l13 = fmaxf(i3 * m3, 0.0f);
                float l14 = tanh_ap(i4 + m4);
                float l15 = sig_ap(i5 + m5);
                float l16 = tanh_ap(i6 + m6);
                float l17 = sig_ap(i7 + m7);
                float l20 = tanh_ap(l10 * l11);
                float l21 = tanh_ap(l12 + l13);
                float l22 = tanh_ap(l14 * l15);
                float l23 = sig_ap(l16 + l17);
                l20 = tanh_ap(l20 + cin);
                float nc  = l20 * l21;
                float l31 = tanh_ap(l22 + l23);
                float nh  = tanh_acc(nc * l31);

                out[(b0 + row) * U_ + u0 + uu] = nh;
            }
        } else {
            // ---- Packed fp16x2 epilogue: 2 row-pairs x 1 unit per thread ---
            unsigned char* prod = prodBase + ((t & 1) ? 0 : 1) * (16 * GRP * 2048);
            const __half2 z2 = __float2half2_rn(0.0f);
            #pragma unroll
            for (int p = 0; p < 2; p++) {
                const int rowA = p * 16 + quad;
                const int rowB = rowA + 8;
                __half2 xv2 = pack2h(Xs[rowA * XPITCH + t],
                                     Xs[rowB * XPITCH + t]);
                __half2 m2[8];
                #pragma unroll
                for (int j = 0; j < 4; j++) {
                    m2[2 * j + 0] = pack2h(acc[p][j][0], acc[p][j][2]);
                    m2[2 * j + 1] = pack2h(acc[p][j][1], acc[p][j][3]);
                }
                __half2 l10 = sig2_ap(__hfma2(xv2, kr2[0], m2[0]));
                __half2 l11 = __hmax2(__hfma2(xv2, kr2[1], m2[1]), z2);
                __half2 l12 = sig2_ap(__hfma2(xv2, kr2[2], m2[2]));
                __half2 l13 = __hmax2(__hmul2(__hmul2(xv2, kr2[3]), m2[3]), z2);
                __half2 l14 = tanh2_ap(__hfma2(xv2, kr2[4], m2[4]));
                __half2 l15 = sig2_ap(__hfma2(xv2, kr2[5], m2[5]));
                __half2 l16 = tanh2_ap(__hfma2(xv2, kr2[6], m2[6]));
                __half2 l17 = sig2_ap(__hfma2(xv2, kr2[7], m2[7]));

                __half2 l20 = tanh2_ap(__hmul2(l10, l11));
                __half2 l21 = tanh2_ap(__hadd2(l12, l13));
                __half2 l22 = tanh2_ap(__hmul2(l14, l15));
                __half2 l23 = sig2_ap(__hadd2(l16, l17));

                l20 = tanh2_ap(__hadd2(l20, c2[p]));
                __half2 nc  = __hmul2(l20, l21);
                __half2 l31 = tanh2_ap(__hadd2(l22, l23));
                __half2 nh  = tanh2_ap(__hmul2(nc, l31));
                c2[p] = nc;

                uint32_t self = *reinterpret_cast<uint32_t*>(&nh);
                uint32_t part = __shfl_xor_sync(0xffffffffu, self, 1);
                if ((ql & 1) == 0) {
                    uint32_t wA, wB;
                    asm("prmt.b32 %0, %1, %2, 0x5410;" : "=r"(wA)
                        : "r"(self), "r"(part));
                    asm("prmt.b32 %0, %1, %2, 0x7632;" : "=r"(wB)
                        : "r"(self), "r"(part));
                    *reinterpret_cast<uint32_t*>(prod + rowA * 64 + uu * 2) = wA;
                    *reinterpret_cast<uint32_t*>(prod + rowB * 64 + uu * 2) = wB;
                }
            }

            __threadfence();        // publish slice stores
            __syncthreads();        // all threads' stores fenced; GEMM t done
            if (tid == 0) {
                asm volatile("st.relaxed.gpu.global.b32 [%0], %1;"
                             :: "l"(flagOwn), "r"((unsigned)(t + 1)) : "memory");
            }
        }
    }

    // ---- Run-end: monotonic ticket barrier, then reset flags for replay ----
    __syncthreads();
    if (tid == 0) {
        unsigned* ctr = &g_arrive[bx * 32];
        __threadfence();
        unsigned ticket = atomicAdd(ctr, 1u);
        unsigned target = (ticket & ~(GRP - 1u)) + GRP;
        volatile unsigned* p = ctr;
        while ((int)(*p - target) < 0) { }
        *flagOwn = 0u;              // safe: all group CTAs past final polls
        __threadfence();
    }
}

extern "C" void kernel_launch(void* const* d_in, const int* in_sizes, int n_in,
                              void* d_out, int out_size) {
    const float* x    = nullptr;
    const float* kern = nullptr;
    const float* W    = nullptr;
    for (int i = 0; i < n_in; i++) {
        if (in_sizes[i] == B_ * U_)       x    = (const float*)d_in[i];
        else if (in_sizes[i] == 8 * U_)   kern = (const float*)d_in[i];
        else if (in_sizes[i] == U_ * NCW) W    = (const float*)d_in[i];
    }
    float* out = (float*)d_out;

    cudaFuncSetAttribute(nas_hmma, cudaFuncAttributeMaxDynamicSharedMemorySize,
                         SMEM_TOTAL);
    nas_hmma<<<NBLK, NTHREADS, SMEM_TOTAL>>>(out, W, kern, x);
}